// round 5
// baseline (speedup 1.0000x reference)
#include <cuda_runtime.h>
#include <math.h>

#define NHEADS 16
#define NSEQ   2048
#define CDIM   1024
#define HD     64
#define D2     128

// ---------------- scratch ----------------
__device__ float g_x[(size_t)NSEQ * CDIM];
__device__ float g_wp[(size_t)CDIM * 2 * CDIM];
__device__ float g_qkv[(size_t)NSEQ * 6 * CDIM];
__device__ float g_q[(size_t)NHEADS * NSEQ * D2];
__device__ float g_k[(size_t)NHEADS * NSEQ * D2];
__device__ float g_v[(size_t)NHEADS * NSEQ * D2];
__device__ float g_S1[(size_t)NHEADS * NSEQ * NSEQ];
__device__ float g_S2[(size_t)NHEADS * NSEQ * NSEQ];
__device__ float g_out2d[(size_t)NSEQ * 2 * CDIM];
__device__ float g_lam;
__device__ int   g_use;

// ---------------- input disambiguation ----------------
__global__ void detect_kernel(const float* __restrict__ bigA, const float* __restrict__ bigB) {
    __shared__ float sa[256], sb[256];
    int t = threadIdx.x;
    float a = 0.f, b = 0.f;
    for (int i = t; i < 4096; i += 256) { a += fabsf(bigA[i]); b += fabsf(bigB[i]); }
    sa[t] = a; sb[t] = b;
    __syncthreads();
    for (int s = 128; s > 0; s >>= 1) {
        if (t < s) { sa[t] += sa[t + s]; sb[t] += sb[t + s]; }
        __syncthreads();
    }
    if (t == 0) g_use = (sb[0] > sa[0]) ? 1 : 0;  // larger-|v| one is x
}

__global__ void route_kernel(const float* __restrict__ bigA, const float* __restrict__ bigB) {
    int u = g_use;
    const float* px = u ? bigB : bigA;
    const float* pw = u ? bigA : bigB;
    size_t n = (size_t)NSEQ * CDIM;
    for (size_t i = (size_t)blockIdx.x * blockDim.x + threadIdx.x; i < n;
         i += (size_t)gridDim.x * blockDim.x) {
        g_x[i]  = px[i];
        g_wp[i] = pw[i];
    }
}

// lam = exp(s0.s2) - exp(s1.s3) + 0.2 (identical under dict or alphabetical order)
__global__ void lam_kernel(const float* __restrict__ s0, const float* __restrict__ s1,
                           const float* __restrict__ s2, const float* __restrict__ s3) {
    __shared__ float sa[64], sb[64];
    int t = threadIdx.x;
    sa[t] = s0[t] * s2[t];
    sb[t] = s1[t] * s3[t];
    __syncthreads();
    for (int s = 32; s > 0; s >>= 1) {
        if (t < s) { sa[t] += sa[t + s]; sb[t] += sb[t + s]; }
        __syncthreads();
    }
    if (t == 0) g_lam = expf(sa[0]) - expf(sb[0]) + 0.2f;
}

// ---------------- 1. qkv[n,d] = sum_c x[n,c] * Wqkv[d,c]  (naive, 1 thread / element) ----------------
__global__ void __launch_bounds__(256) qkv_naive(const float* __restrict__ Wqkv) {
    int d = blockIdx.x * 256 + threadIdx.x;   // 0..6143
    int n = blockIdx.y;                        // 0..2047
    const float* xr = g_x + (size_t)n * CDIM;
    const float* wr = Wqkv + (size_t)d * CDIM;
    float acc = 0.f;
    for (int c = 0; c < CDIM; c++) acc += xr[c] * wr[c];
    g_qkv[(size_t)n * (6 * CDIM) + d] = acc;
}

// ---------------- 2. reorg + RoPE (double-precision trig) ----------------
// q = concat(qkv[s=0], qkv[s=1]) ; q' = q*cos(emb) + rotate_half(q)*sin(emb)
// emb[n,d] = n * 10000^(-(d mod 64)/64)
__global__ void __launch_bounds__(64) rope_naive() {
    int n = blockIdx.x;
    int h = blockIdx.y;
    int e = threadIdx.x;  // 0..63
    const float* row = g_qkv + (size_t)n * (6 * CDIM);
    int base = h * HD + e;
    float qa = row[0 * CDIM + base];   // q[..., e]
    float qb = row[1 * CDIM + base];   // q[..., 64+e]
    float ka = row[2 * CDIM + base];
    float kb = row[3 * CDIM + base];
    float va = row[4 * CDIM + base];
    float vb = row[5 * CDIM + base];

    double invf = exp(-(double)e * (9.210340371976184 / 64.0));  // 10000^(-e/64)
    double th = (double)n * invf;
    float c = (float)cos(th);
    float s = (float)sin(th);

    size_t o = ((size_t)h * NSEQ + n) * D2;
    // d = e (<64):    q*cos - q[d+64]*sin
    g_q[o + e]      = qa * c - qb * s;
    // d = 64+e:       q*cos + q[d-64]*sin
    g_q[o + 64 + e] = qb * c + qa * s;
    g_k[o + e]      = ka * c - kb * s;
    g_k[o + 64 + e] = kb * c + ka * s;
    g_v[o + e]      = va;
    g_v[o + 64 + e] = vb;
}

// ---------------- 3. scores (naive): S1[h,i,j], S2[h,i,j] ----------------
__global__ void __launch_bounds__(128) scores_naive() {
    int j = blockIdx.x * 128 + threadIdx.x;  // 0..2047
    int i = blockIdx.y;                       // 0..2047
    int h = blockIdx.z;                       // 0..15
    const float* qr = g_q + ((size_t)h * NSEQ + i) * D2;
    const float* kr = g_k + ((size_t)h * NSEQ + j) * D2;
    float a1 = 0.f, a2 = 0.f;
    for (int e = 0; e < 64; e++) {
        a1 += qr[e]      * kr[e];
        a2 += qr[64 + e] * kr[64 + e];
    }
    size_t o = ((size_t)h * NSEQ + i) * NSEQ + j;
    g_S1[o] = a1 * 0.125f;
    g_S2[o] = a2 * 0.125f;
}

// ---------------- 4. softmax diff: one warp per row ----------------
__global__ void __launch_bounds__(32) softmax_naive() {
    size_t row = blockIdx.x;  // 0 .. H*N-1
    float* s1 = g_S1 + row * NSEQ;
    float* s2 = g_S2 + row * NSEQ;
    int lane = threadIdx.x;

    float m1 = -1e30f, m2 = -1e30f;
    for (int k = lane; k < NSEQ; k += 32) {
        m1 = fmaxf(m1, s1[k]);
        m2 = fmaxf(m2, s2[k]);
    }
    #pragma unroll
    for (int o = 16; o > 0; o >>= 1) {
        m1 = fmaxf(m1, __shfl_xor_sync(0xffffffffu, m1, o));
        m2 = fmaxf(m2, __shfl_xor_sync(0xffffffffu, m2, o));
    }
    float l1 = 0.f, l2 = 0.f;
    for (int k = lane; k < NSEQ; k += 32) {
        l1 += __expf(s1[k] - m1);
        l2 += __expf(s2[k] - m2);
    }
    #pragma unroll
    for (int o = 16; o > 0; o >>= 1) {
        l1 += __shfl_xor_sync(0xffffffffu, l1, o);
        l2 += __shfl_xor_sync(0xffffffffu, l2, o);
    }
    float r1 = 1.0f / l1;
    float r2 = g_lam / l2;
    for (int k = lane; k < NSEQ; k += 32) {
        float p1 = __expf(s1[k] - m1) * r1;
        float p2 = __expf(s2[k] - m2) * r2;
        s1[k] = p1 - p2;
    }
}

// ---------------- 5. out2d[n, h*128+d] = sum_j P[h,n,j] * V[h,j,d] ----------------
__global__ void __launch_bounds__(128) pv_naive() {
    int d = threadIdx.x;   // 0..127
    int n = blockIdx.x;    // 0..2047
    int h = blockIdx.y;    // 0..15
    const float* pr = g_S1 + ((size_t)h * NSEQ + n) * NSEQ;
    const float* vb = g_v + (size_t)h * NSEQ * D2;
    float acc = 0.f;
    for (int j = 0; j < NSEQ; j++)
        acc += pr[j] * vb[(size_t)j * D2 + d];
    g_out2d[(size_t)n * (2 * CDIM) + h * D2 + d] = acc;
}

// ---------------- 6. out[n,c] = sum_d out2d[n,d] * Wp[c,d] ----------------
__global__ void __launch_bounds__(256) proj_naive(float* __restrict__ out) {
    int c = blockIdx.x * 256 + threadIdx.x;  // 0..1023
    int n = blockIdx.y;                       // 0..2047
    const float* orow = g_out2d + (size_t)n * (2 * CDIM);
    const float* wrow = g_wp + (size_t)c * (2 * CDIM);
    float acc = 0.f;
    for (int d = 0; d < 2 * CDIM; d++) acc += orow[d] * wrow[d];
    out[(size_t)n * CDIM + c] = acc;
}

// ---------------- launch ----------------
extern "C" void kernel_launch(void* const* d_in, const int* in_sizes, int n_in,
                              void* d_out, int out_size) {
    const float* Wqkv = 0;
    const float* bigs[2] = {0, 0};
    const float* smalls[4] = {0, 0, 0, 0};
    int nbig = 0, nsmall = 0;
    for (int i = 0; i < n_in; i++) {
        const float* p = (const float*)d_in[i];
        if (in_sizes[i] == 6 * CDIM * CDIM) Wqkv = p;
        else if (in_sizes[i] == 2 * CDIM * CDIM) { if (nbig < 2) bigs[nbig++] = p; }
        else if (in_sizes[i] == HD) { if (nsmall < 4) smalls[nsmall++] = p; }
    }
    if (!Wqkv || nbig < 2 || nsmall < 4) {  // positional fallback (dict order)
        bigs[0]   = (const float*)d_in[0];
        Wqkv      = (const float*)d_in[1];
        bigs[1]   = (const float*)d_in[2];
        smalls[0] = (const float*)d_in[3];
        smalls[1] = (const float*)d_in[4];
        smalls[2] = (const float*)d_in[5];
        smalls[3] = (const float*)d_in[6];
    }
    float* out = (float*)d_out;

    detect_kernel<<<1, 256>>>(bigs[0], bigs[1]);
    route_kernel<<<512, 256>>>(bigs[0], bigs[1]);
    lam_kernel<<<1, 64>>>(smalls[0], smalls[1], smalls[2], smalls[3]);

    qkv_naive<<<dim3(24, NSEQ), 256>>>(Wqkv);
    rope_naive<<<dim3(NSEQ, NHEADS), 64>>>();
    scores_naive<<<dim3(16, NSEQ, NHEADS), 128>>>();
    softmax_naive<<<NHEADS * NSEQ, 32>>>();
    pv_naive<<<dim3(NSEQ, NHEADS), 128>>>();
    proj_naive<<<dim3(4, NSEQ), 256>>>(out);
}

// round 6
// speedup vs baseline: 1.3830x; 1.3830x over previous
#include <cuda_runtime.h>
#include <math.h>

#define NHEADS 16
#define NSEQ   2048
#define CDIM   1024
#define HD     64
#define D2     128

// ---------------- scratch ----------------
__device__ float g_x[(size_t)NSEQ * CDIM];
__device__ float g_wp[(size_t)CDIM * 2 * CDIM];
__device__ float g_qkv[(size_t)NSEQ * 6 * CDIM];
__device__ float g_q[(size_t)NHEADS * NSEQ * D2];
__device__ float g_k[(size_t)NHEADS * NSEQ * D2];
__device__ float g_v[(size_t)NHEADS * NSEQ * D2];
__device__ float g_S1[(size_t)NHEADS * NSEQ * NSEQ];
__device__ float g_S2[(size_t)NHEADS * NSEQ * NSEQ];
__device__ float g_out2d[(size_t)NSEQ * 2 * CDIM];
__device__ float g_lam;
__device__ int   g_use;

// ---------------- input disambiguation (verbatim from passing round 5) ----------------
__global__ void detect_kernel(const float* __restrict__ bigA, const float* __restrict__ bigB) {
    __shared__ float sa[256], sb[256];
    int t = threadIdx.x;
    float a = 0.f, b = 0.f;
    for (int i = t; i < 4096; i += 256) { a += fabsf(bigA[i]); b += fabsf(bigB[i]); }
    sa[t] = a; sb[t] = b;
    __syncthreads();
    for (int s = 128; s > 0; s >>= 1) {
        if (t < s) { sa[t] += sa[t + s]; sb[t] += sb[t + s]; }
        __syncthreads();
    }
    if (t == 0) g_use = (sb[0] > sa[0]) ? 1 : 0;
}

__global__ void route_kernel(const float* __restrict__ bigA, const float* __restrict__ bigB) {
    int u = g_use;
    const float* px = u ? bigB : bigA;
    const float* pw = u ? bigA : bigB;
    size_t n = (size_t)NSEQ * CDIM;
    for (size_t i = (size_t)blockIdx.x * blockDim.x + threadIdx.x; i < n;
         i += (size_t)gridDim.x * blockDim.x) {
        g_x[i]  = px[i];
        g_wp[i] = pw[i];
    }
}

__global__ void lam_kernel(const float* __restrict__ s0, const float* __restrict__ s1,
                           const float* __restrict__ s2, const float* __restrict__ s3) {
    __shared__ float sa[64], sb[64];
    int t = threadIdx.x;
    sa[t] = s0[t] * s2[t];
    sb[t] = s1[t] * s3[t];
    __syncthreads();
    for (int s = 32; s > 0; s >>= 1) {
        if (t < s) { sa[t] += sa[t + s]; sb[t] += sb[t + s]; }
        __syncthreads();
    }
    if (t == 0) g_lam = expf(sa[0]) - expf(sb[0]) + 0.2f;
}

// ---------------- 1. qkv (verbatim from round 5) ----------------
__global__ void __launch_bounds__(256) qkv_naive(const float* __restrict__ Wqkv) {
    int d = blockIdx.x * 256 + threadIdx.x;
    int n = blockIdx.y;
    const float* xr = g_x + (size_t)n * CDIM;
    const float* wr = Wqkv + (size_t)d * CDIM;
    float acc = 0.f;
    for (int c = 0; c < CDIM; c++) acc += xr[c] * wr[c];
    g_qkv[(size_t)n * (6 * CDIM) + d] = acc;
}

// ---------------- 2. reorg + RoPE (verbatim from round 5) ----------------
__global__ void __launch_bounds__(64) rope_naive() {
    int n = blockIdx.x;
    int h = blockIdx.y;
    int e = threadIdx.x;
    const float* row = g_qkv + (size_t)n * (6 * CDIM);
    int base = h * HD + e;
    float qa = row[0 * CDIM + base];
    float qb = row[1 * CDIM + base];
    float ka = row[2 * CDIM + base];
    float kb = row[3 * CDIM + base];
    float va = row[4 * CDIM + base];
    float vb = row[5 * CDIM + base];

    double invf = exp(-(double)e * (9.210340371976184 / 64.0));
    double th = (double)n * invf;
    float c = (float)cos(th);
    float s = (float)sin(th);

    size_t o = ((size_t)h * NSEQ + n) * D2;
    g_q[o + e]      = qa * c - qb * s;
    g_q[o + 64 + e] = qb * c + qa * s;
    g_k[o + e]      = ka * c - kb * s;
    g_k[o + 64 + e] = kb * c + ka * s;
    g_v[o + e]      = va;
    g_v[o + 64 + e] = vb;
}

// ---------------- 3. scores TILED: S1[h,i,j]=0.125*q1_i.k1_j, S2 likewise ----------------
// 64x64 output tile per block, 256 threads, 4x4 per thread, smem-staged.
__global__ void __launch_bounds__(256) scores_tiled() {
    int h = blockIdx.z;
    int k0 = blockIdx.x * 64;   // key-block
    int q0 = blockIdx.y * 64;   // query-block
    __shared__ float qs[64][65];   // [q-row][dim 0..127 staged per half]
    __shared__ float ks[64][65];
    int tid = threadIdx.x;
    int ty = tid >> 4, tx = tid & 15;

    const float* qb = g_q + ((size_t)h * NSEQ + q0) * D2;
    const float* kb = g_k + ((size_t)h * NSEQ + k0) * D2;

    float a1[4][4] = {}, a2[4][4] = {};
    #pragma unroll
    for (int half = 0; half < 2; half++) {
        for (int i = tid; i < 64 * 64; i += 256) {
            int r = i >> 6, c = i & 63;
            qs[r][c] = qb[(size_t)r * D2 + half * 64 + c];
            ks[r][c] = kb[(size_t)r * D2 + half * 64 + c];
        }
        __syncthreads();
        #pragma unroll 8
        for (int k = 0; k < 64; k++) {
            float ar[4], br[4];
            #pragma unroll
            for (int i = 0; i < 4; i++) ar[i] = qs[ty * 4 + i][k];
            #pragma unroll
            for (int j = 0; j < 4; j++) br[j] = ks[tx * 4 + j][k];
            if (half == 0) {
                #pragma unroll
                for (int i = 0; i < 4; i++)
                    #pragma unroll
                    for (int j = 0; j < 4; j++)
                        a1[i][j] += ar[i] * br[j];
            } else {
                #pragma unroll
                for (int i = 0; i < 4; i++)
                    #pragma unroll
                    for (int j = 0; j < 4; j++)
                        a2[i][j] += ar[i] * br[j];
            }
        }
        __syncthreads();
    }

    #pragma unroll
    for (int i = 0; i < 4; i++) {
        size_t rowidx = ((size_t)h * NSEQ + q0 + ty * 4 + i) * NSEQ + k0 + tx * 4;
        #pragma unroll
        for (int j = 0; j < 4; j++) {
            g_S1[rowidx + j] = a1[i][j] * 0.125f;
            g_S2[rowidx + j] = a2[i][j] * 0.125f;
        }
    }
}

// ---------------- 4. softmax diff, 256 threads/row, exp once ----------------
__global__ void __launch_bounds__(256) softmax_diff256() {
    size_t row = blockIdx.x;  // 0 .. H*N-1
    float* s1 = g_S1 + row * NSEQ;
    float* s2 = g_S2 + row * NSEQ;
    int tid = threadIdx.x;
    int lane = tid & 31, warp = tid >> 5;
    __shared__ float wr1[8], wr2[8];

    float v1[8], v2[8];
    float m1 = -1e30f, m2 = -1e30f;
    #pragma unroll
    for (int t = 0; t < 8; t++) {
        v1[t] = s1[tid + t * 256];
        v2[t] = s2[tid + t * 256];
        m1 = fmaxf(m1, v1[t]);
        m2 = fmaxf(m2, v2[t]);
    }
    #pragma unroll
    for (int o = 16; o > 0; o >>= 1) {
        m1 = fmaxf(m1, __shfl_xor_sync(0xffffffffu, m1, o));
        m2 = fmaxf(m2, __shfl_xor_sync(0xffffffffu, m2, o));
    }
    if (lane == 0) { wr1[warp] = m1; wr2[warp] = m2; }
    __syncthreads();
    m1 = wr1[0]; m2 = wr2[0];
    #pragma unroll
    for (int w = 1; w < 8; w++) { m1 = fmaxf(m1, wr1[w]); m2 = fmaxf(m2, wr2[w]); }
    __syncthreads();

    float l1 = 0.f, l2 = 0.f;
    #pragma unroll
    for (int t = 0; t < 8; t++) {
        v1[t] = __expf(v1[t] - m1);
        v2[t] = __expf(v2[t] - m2);
        l1 += v1[t];
        l2 += v2[t];
    }
    #pragma unroll
    for (int o = 16; o > 0; o >>= 1) {
        l1 += __shfl_xor_sync(0xffffffffu, l1, o);
        l2 += __shfl_xor_sync(0xffffffffu, l2, o);
    }
    if (lane == 0) { wr1[warp] = l1; wr2[warp] = l2; }
    __syncthreads();
    l1 = 0.f; l2 = 0.f;
    #pragma unroll
    for (int w = 0; w < 8; w++) { l1 += wr1[w]; l2 += wr2[w]; }

    float r1 = 1.0f / l1;
    float r2 = g_lam / l2;
    #pragma unroll
    for (int t = 0; t < 8; t++)
        s1[tid + t * 256] = v1[t] * r1 - v2[t] * r2;
}

// ---------------- 5. PV (verbatim from round 5) ----------------
__global__ void __launch_bounds__(128) pv_naive() {
    int d = threadIdx.x;
    int n = blockIdx.x;
    int h = blockIdx.y;
    const float* pr = g_S1 + ((size_t)h * NSEQ + n) * NSEQ;
    const float* vb = g_v + (size_t)h * NSEQ * D2;
    float acc = 0.f;
    for (int j = 0; j < NSEQ; j++)
        acc += pr[j] * vb[(size_t)j * D2 + d];
    g_out2d[(size_t)n * (2 * CDIM) + h * D2 + d] = acc;
}

// ---------------- 6. proj (verbatim from round 5) ----------------
__global__ void __launch_bounds__(256) proj_naive(float* __restrict__ out) {
    int c = blockIdx.x * 256 + threadIdx.x;
    int n = blockIdx.y;
    const float* orow = g_out2d + (size_t)n * (2 * CDIM);
    const float* wrow = g_wp + (size_t)c * (2 * CDIM);
    float acc = 0.f;
    for (int d = 0; d < 2 * CDIM; d++) acc += orow[d] * wrow[d];
    out[(size_t)n * CDIM + c] = acc;
}

// ---------------- launch ----------------
extern "C" void kernel_launch(void* const* d_in, const int* in_sizes, int n_in,
                              void* d_out, int out_size) {
    const float* Wqkv = 0;
    const float* bigs[2] = {0, 0};
    const float* smalls[4] = {0, 0, 0, 0};
    int nbig = 0, nsmall = 0;
    for (int i = 0; i < n_in; i++) {
        const float* p = (const float*)d_in[i];
        if (in_sizes[i] == 6 * CDIM * CDIM) Wqkv = p;
        else if (in_sizes[i] == 2 * CDIM * CDIM) { if (nbig < 2) bigs[nbig++] = p; }
        else if (in_sizes[i] == HD) { if (nsmall < 4) smalls[nsmall++] = p; }
    }
    if (!Wqkv || nbig < 2 || nsmall < 4) {
        bigs[0]   = (const float*)d_in[0];
        Wqkv      = (const float*)d_in[1];
        bigs[1]   = (const float*)d_in[2];
        smalls[0] = (const float*)d_in[3];
        smalls[1] = (const float*)d_in[4];
        smalls[2] = (const float*)d_in[5];
        smalls[3] = (const float*)d_in[6];
    }
    float* out = (float*)d_out;

    detect_kernel<<<1, 256>>>(bigs[0], bigs[1]);
    route_kernel<<<512, 256>>>(bigs[0], bigs[1]);
    lam_kernel<<<1, 64>>>(smalls[0], smalls[1], smalls[2], smalls[3]);

    qkv_naive<<<dim3(24, NSEQ), 256>>>(Wqkv);
    rope_naive<<<dim3(NSEQ, NHEADS), 64>>>();
    scores_tiled<<<dim3(32, 32, NHEADS), 256>>>();
    softmax_diff256<<<NHEADS * NSEQ, 256>>>();
    pv_naive<<<dim3(NSEQ, NHEADS), 128>>>();
    proj_naive<<<dim3(4, NSEQ), 256>>>(out);
}

// round 7
// speedup vs baseline: 31.1137x; 22.4973x over previous
#include <cuda_runtime.h>
#include <math.h>

#define NHEADS 16
#define NSEQ   2048
#define CDIM   1024
#define HD     64
#define D2     128

// ---------------- scratch ----------------
__device__ float g_x[(size_t)NSEQ * CDIM];
__device__ float g_wp[(size_t)CDIM * 2 * CDIM];
__device__ float g_qkv[(size_t)NSEQ * 6 * CDIM];
__device__ float g_q[(size_t)NHEADS * NSEQ * D2];
__device__ float g_k[(size_t)NHEADS * NSEQ * D2];
__device__ float g_v[(size_t)NHEADS * NSEQ * D2];
__device__ float g_S1[(size_t)NHEADS * NSEQ * NSEQ];
__device__ float g_S2[(size_t)NHEADS * NSEQ * NSEQ];
__device__ float g_out2d[(size_t)NSEQ * 2 * CDIM];
__device__ float g_lam;
__device__ int   g_use;

// ---------------- input disambiguation (verbatim, validated) ----------------
__global__ void detect_kernel(const float* __restrict__ bigA, const float* __restrict__ bigB) {
    __shared__ float sa[256], sb[256];
    int t = threadIdx.x;
    float a = 0.f, b = 0.f;
    for (int i = t; i < 4096; i += 256) { a += fabsf(bigA[i]); b += fabsf(bigB[i]); }
    sa[t] = a; sb[t] = b;
    __syncthreads();
    for (int s = 128; s > 0; s >>= 1) {
        if (t < s) { sa[t] += sa[t + s]; sb[t] += sb[t + s]; }
        __syncthreads();
    }
    if (t == 0) g_use = (sb[0] > sa[0]) ? 1 : 0;
}

__global__ void route_kernel(const float* __restrict__ bigA, const float* __restrict__ bigB) {
    int u = g_use;
    const float* px = u ? bigB : bigA;
    const float* pw = u ? bigA : bigB;
    size_t n = (size_t)NSEQ * CDIM;
    for (size_t i = (size_t)blockIdx.x * blockDim.x + threadIdx.x; i < n;
         i += (size_t)gridDim.x * blockDim.x) {
        g_x[i]  = px[i];
        g_wp[i] = pw[i];
    }
}

__global__ void lam_kernel(const float* __restrict__ s0, const float* __restrict__ s1,
                           const float* __restrict__ s2, const float* __restrict__ s3) {
    __shared__ float sa[64], sb[64];
    int t = threadIdx.x;
    sa[t] = s0[t] * s2[t];
    sb[t] = s1[t] * s3[t];
    __syncthreads();
    for (int s = 32; s > 0; s >>= 1) {
        if (t < s) { sa[t] += sa[t + s]; sb[t] += sb[t + s]; }
        __syncthreads();
    }
    if (t == 0) g_lam = expf(sa[0]) - expf(sb[0]) + 0.2f;
}

// ---------------- 1. qkv TILED: qkv[n,d] = sum_c x[n,c]*Wqkv[d,c] ----------------
// NT GEMM, 64x64 tile, k-step 64, structure cloned from validated scores_tiled.
__global__ void __launch_bounds__(256) qkv_tiled(const float* __restrict__ Wqkv) {
    int d0 = blockIdx.x * 64;   // output col block (d)
    int n0 = blockIdx.y * 64;   // output row block (n)
    __shared__ float As[64][65];
    __shared__ float Bs[64][65];
    int tid = threadIdx.x;
    int ty = tid >> 4, tx = tid & 15;

    float acc[4][4] = {};
    for (int kt = 0; kt < CDIM; kt += 64) {
        for (int i = tid; i < 64 * 64; i += 256) {
            int r = i >> 6, c = i & 63;
            As[r][c] = g_x[(size_t)(n0 + r) * CDIM + kt + c];
            Bs[r][c] = Wqkv[(size_t)(d0 + r) * CDIM + kt + c];
        }
        __syncthreads();
        #pragma unroll 8
        for (int k = 0; k < 64; k++) {
            float ar[4], br[4];
            #pragma unroll
            for (int i = 0; i < 4; i++) ar[i] = As[ty * 4 + i][k];
            #pragma unroll
            for (int j = 0; j < 4; j++) br[j] = Bs[tx * 4 + j][k];
            #pragma unroll
            for (int i = 0; i < 4; i++)
                #pragma unroll
                for (int j = 0; j < 4; j++)
                    acc[i][j] += ar[i] * br[j];
        }
        __syncthreads();
    }
    #pragma unroll
    for (int i = 0; i < 4; i++)
        #pragma unroll
        for (int j = 0; j < 4; j++)
            g_qkv[(size_t)(n0 + ty * 4 + i) * (6 * CDIM) + d0 + tx * 4 + j] = acc[i][j];
}

// ---------------- 2. reorg + RoPE (verbatim, validated) ----------------
__global__ void __launch_bounds__(64) rope_naive() {
    int n = blockIdx.x;
    int h = blockIdx.y;
    int e = threadIdx.x;
    const float* row = g_qkv + (size_t)n * (6 * CDIM);
    int base = h * HD + e;
    float qa = row[0 * CDIM + base];
    float qb = row[1 * CDIM + base];
    float ka = row[2 * CDIM + base];
    float kb = row[3 * CDIM + base];
    float va = row[4 * CDIM + base];
    float vb = row[5 * CDIM + base];

    double invf = exp(-(double)e * (9.210340371976184 / 64.0));
    double th = (double)n * invf;
    float c = (float)cos(th);
    float s = (float)sin(th);

    size_t o = ((size_t)h * NSEQ + n) * D2;
    g_q[o + e]      = qa * c - qb * s;
    g_q[o + 64 + e] = qb * c + qa * s;
    g_k[o + e]      = ka * c - kb * s;
    g_k[o + 64 + e] = kb * c + ka * s;
    g_v[o + e]      = va;
    g_v[o + 64 + e] = vb;
}

// ---------------- 3. scores TILED (verbatim, validated) ----------------
__global__ void __launch_bounds__(256) scores_tiled() {
    int h = blockIdx.z;
    int k0 = blockIdx.x * 64;
    int q0 = blockIdx.y * 64;
    __shared__ float qs[64][65];
    __shared__ float ks[64][65];
    int tid = threadIdx.x;
    int ty = tid >> 4, tx = tid & 15;

    const float* qb = g_q + ((size_t)h * NSEQ + q0) * D2;
    const float* kb = g_k + ((size_t)h * NSEQ + k0) * D2;

    float a1[4][4] = {}, a2[4][4] = {};
    #pragma unroll
    for (int half = 0; half < 2; half++) {
        for (int i = tid; i < 64 * 64; i += 256) {
            int r = i >> 6, c = i & 63;
            qs[r][c] = qb[(size_t)r * D2 + half * 64 + c];
            ks[r][c] = kb[(size_t)r * D2 + half * 64 + c];
        }
        __syncthreads();
        #pragma unroll 8
        for (int k = 0; k < 64; k++) {
            float ar[4], br[4];
            #pragma unroll
            for (int i = 0; i < 4; i++) ar[i] = qs[ty * 4 + i][k];
            #pragma unroll
            for (int j = 0; j < 4; j++) br[j] = ks[tx * 4 + j][k];
            if (half == 0) {
                #pragma unroll
                for (int i = 0; i < 4; i++)
                    #pragma unroll
                    for (int j = 0; j < 4; j++)
                        a1[i][j] += ar[i] * br[j];
            } else {
                #pragma unroll
                for (int i = 0; i < 4; i++)
                    #pragma unroll
                    for (int j = 0; j < 4; j++)
                        a2[i][j] += ar[i] * br[j];
            }
        }
        __syncthreads();
    }

    #pragma unroll
    for (int i = 0; i < 4; i++) {
        size_t rowidx = ((size_t)h * NSEQ + q0 + ty * 4 + i) * NSEQ + k0 + tx * 4;
        #pragma unroll
        for (int j = 0; j < 4; j++) {
            g_S1[rowidx + j] = a1[i][j] * 0.125f;
            g_S2[rowidx + j] = a2[i][j] * 0.125f;
        }
    }
}

// ---------------- 4. softmax diff (verbatim, validated) ----------------
__global__ void __launch_bounds__(256) softmax_diff256() {
    size_t row = blockIdx.x;
    float* s1 = g_S1 + row * NSEQ;
    float* s2 = g_S2 + row * NSEQ;
    int tid = threadIdx.x;
    int lane = tid & 31, warp = tid >> 5;
    __shared__ float wr1[8], wr2[8];

    float v1[8], v2[8];
    float m1 = -1e30f, m2 = -1e30f;
    #pragma unroll
    for (int t = 0; t < 8; t++) {
        v1[t] = s1[tid + t * 256];
        v2[t] = s2[tid + t * 256];
        m1 = fmaxf(m1, v1[t]);
        m2 = fmaxf(m2, v2[t]);
    }
    #pragma unroll
    for (int o = 16; o > 0; o >>= 1) {
        m1 = fmaxf(m1, __shfl_xor_sync(0xffffffffu, m1, o));
        m2 = fmaxf(m2, __shfl_xor_sync(0xffffffffu, m2, o));
    }
    if (lane == 0) { wr1[warp] = m1; wr2[warp] = m2; }
    __syncthreads();
    m1 = wr1[0]; m2 = wr2[0];
    #pragma unroll
    for (int w = 1; w < 8; w++) { m1 = fmaxf(m1, wr1[w]); m2 = fmaxf(m2, wr2[w]); }
    __syncthreads();

    float l1 = 0.f, l2 = 0.f;
    #pragma unroll
    for (int t = 0; t < 8; t++) {
        v1[t] = __expf(v1[t] - m1);
        v2[t] = __expf(v2[t] - m2);
        l1 += v1[t];
        l2 += v2[t];
    }
    #pragma unroll
    for (int o = 16; o > 0; o >>= 1) {
        l1 += __shfl_xor_sync(0xffffffffu, l1, o);
        l2 += __shfl_xor_sync(0xffffffffu, l2, o);
    }
    if (lane == 0) { wr1[warp] = l1; wr2[warp] = l2; }
    __syncthreads();
    l1 = 0.f; l2 = 0.f;
    #pragma unroll
    for (int w = 0; w < 8; w++) { l1 += wr1[w]; l2 += wr2[w]; }

    float r1 = 1.0f / l1;
    float r2 = g_lam / l2;
    #pragma unroll
    for (int t = 0; t < 8; t++)
        s1[tid + t * 256] = v1[t] * r1 - v2[t] * r2;
}

// ---------------- 5. PV TILED: out2d[n, h*128+d] = sum_j P[h,n,j]*V[h,j,d] ----------------
// NN GEMM per head: [2048 x 2048] @ [2048 x 128]. 64x64 tile, k-step 64.
__global__ void __launch_bounds__(256) pv_tiled() {
    int h  = blockIdx.z;
    int d0 = blockIdx.x * 64;   // 0 or 64
    int n0 = blockIdx.y * 64;
    __shared__ float As[64][65];
    __shared__ float Bs[64][65];
    int tid = threadIdx.x;
    int ty = tid >> 4, tx = tid & 15;

    const float* P = g_S1 + (size_t)h * NSEQ * NSEQ;
    const float* V = g_v  + (size_t)h * NSEQ * D2;

    float acc[4][4] = {};
    for (int kt = 0; kt < NSEQ; kt += 64) {
        for (int i = tid; i < 64 * 64; i += 256) {
            int r = i >> 6, c = i & 63;
            As[r][c] = P[(size_t)(n0 + r) * NSEQ + kt + c];
            Bs[r][c] = V[(size_t)(kt + r) * D2 + d0 + c];
        }
        __syncthreads();
        #pragma unroll 8
        for (int k = 0; k < 64; k++) {
            float ar[4], br[4];
            #pragma unroll
            for (int i = 0; i < 4; i++) ar[i] = As[ty * 4 + i][k];
            #pragma unroll
            for (int j = 0; j < 4; j++) br[j] = Bs[k][tx * 4 + j];
            #pragma unroll
            for (int i = 0; i < 4; i++)
                #pragma unroll
                for (int j = 0; j < 4; j++)
                    acc[i][j] += ar[i] * br[j];
        }
        __syncthreads();
    }
    #pragma unroll
    for (int i = 0; i < 4; i++)
        #pragma unroll
        for (int j = 0; j < 4; j++)
            g_out2d[(size_t)(n0 + ty * 4 + i) * (2 * CDIM) + h * D2 + d0 + tx * 4 + j] = acc[i][j];
}

// ---------------- 6. proj TILED: out[n,c] = sum_d out2d[n,d]*Wp[c,d] ----------------
// NT GEMM: [2048 x 2048] @ [1024 x 2048]^T. 64x64 tile, k-step 64.
__global__ void __launch_bounds__(256) proj_tiled(float* __restrict__ out) {
    int c0 = blockIdx.x * 64;
    int n0 = blockIdx.y * 64;
    __shared__ float As[64][65];
    __shared__ float Bs[64][65];
    int tid = threadIdx.x;
    int ty = tid >> 4, tx = tid & 15;

    float acc[4][4] = {};
    for (int kt = 0; kt < 2 * CDIM; kt += 64) {
        for (int i = tid; i < 64 * 64; i += 256) {
            int r = i >> 6, c = i & 63;
            As[r][c] = g_out2d[(size_t)(n0 + r) * (2 * CDIM) + kt + c];
            Bs[r][c] = g_wp[(size_t)(c0 + r) * (2 * CDIM) + kt + c];
        }
        __syncthreads();
        #pragma unroll 8
        for (int k = 0; k < 64; k++) {
            float ar[4], br[4];
            #pragma unroll
            for (int i = 0; i < 4; i++) ar[i] = As[ty * 4 + i][k];
            #pragma unroll
            for (int j = 0; j < 4; j++) br[j] = Bs[tx * 4 + j][k];
            #pragma unroll
            for (int i = 0; i < 4; i++)
                #pragma unroll
                for (int j = 0; j < 4; j++)
                    acc[i][j] += ar[i] * br[j];
        }
        __syncthreads();
    }
    #pragma unroll
    for (int i = 0; i < 4; i++)
        #pragma unroll
        for (int j = 0; j < 4; j++)
            out[(size_t)(n0 + ty * 4 + i) * CDIM + c0 + tx * 4 + j] = acc[i][j];
}

// ---------------- launch ----------------
extern "C" void kernel_launch(void* const* d_in, const int* in_sizes, int n_in,
                              void* d_out, int out_size) {
    const float* Wqkv = 0;
    const float* bigs[2] = {0, 0};
    const float* smalls[4] = {0, 0, 0, 0};
    int nbig = 0, nsmall = 0;
    for (int i = 0; i < n_in; i++) {
        const float* p = (const float*)d_in[i];
        if (in_sizes[i] == 6 * CDIM * CDIM) Wqkv = p;
        else if (in_sizes[i] == 2 * CDIM * CDIM) { if (nbig < 2) bigs[nbig++] = p; }
        else if (in_sizes[i] == HD) { if (nsmall < 4) smalls[nsmall++] = p; }
    }
    if (!Wqkv || nbig < 2 || nsmall < 4) {
        bigs[0]   = (const float*)d_in[0];
        Wqkv      = (const float*)d_in[1];
        bigs[1]   = (const float*)d_in[2];
        smalls[0] = (const float*)d_in[3];
        smalls[1] = (const float*)d_in[4];
        smalls[2] = (const float*)d_in[5];
        smalls[3] = (const float*)d_in[6];
    }
    float* out = (float*)d_out;

    detect_kernel<<<1, 256>>>(bigs[0], bigs[1]);
    route_kernel<<<512, 256>>>(bigs[0], bigs[1]);
    lam_kernel<<<1, 64>>>(smalls[0], smalls[1], smalls[2], smalls[3]);

    qkv_tiled<<<dim3(96, 32), 256>>>(Wqkv);               // [2048,6144]
    rope_naive<<<dim3(NSEQ, NHEADS), 64>>>();
    scores_tiled<<<dim3(32, 32, NHEADS), 256>>>();
    softmax_diff256<<<NHEADS * NSEQ, 256>>>();
    pv_tiled<<<dim3(2, 32, NHEADS), 256>>>();             // [2048,128] per head
    proj_tiled<<<dim3(16, 32), 256>>>(out);               // [2048,1024]
}

// round 8
// speedup vs baseline: 32.3962x; 1.0412x over previous
#include <cuda_runtime.h>
#include <math.h>

#define NHEADS 16
#define NSEQ   2048
#define CDIM   1024
#define HD     64
#define D2     128

// ---------------- scratch ----------------
__device__ float g_x[(size_t)NSEQ * CDIM];
__device__ float g_wp[(size_t)CDIM * 2 * CDIM];
__device__ float g_qkv[(size_t)NSEQ * 6 * CDIM];
__device__ float g_q[(size_t)NHEADS * NSEQ * D2];
__device__ float g_k[(size_t)NHEADS * NSEQ * D2];
__device__ float g_v[(size_t)NHEADS * NSEQ * D2];
__device__ float g_S1[(size_t)NHEADS * NSEQ * NSEQ];
__device__ float g_S2[(size_t)NHEADS * NSEQ * NSEQ];
__device__ float g_out2d[(size_t)NSEQ * 2 * CDIM];
__device__ float g_lam;
__device__ int   g_use;

// ---------------- input disambiguation (verbatim, validated) ----------------
__global__ void detect_kernel(const float* __restrict__ bigA, const float* __restrict__ bigB) {
    __shared__ float sa[256], sb[256];
    int t = threadIdx.x;
    float a = 0.f, b = 0.f;
    for (int i = t; i < 4096; i += 256) { a += fabsf(bigA[i]); b += fabsf(bigB[i]); }
    sa[t] = a; sb[t] = b;
    __syncthreads();
    for (int s = 128; s > 0; s >>= 1) {
        if (t < s) { sa[t] += sa[t + s]; sb[t] += sb[t + s]; }
        __syncthreads();
    }
    if (t == 0) g_use = (sb[0] > sa[0]) ? 1 : 0;
}

__global__ void route_kernel(const float* __restrict__ bigA, const float* __restrict__ bigB) {
    int u = g_use;
    const float* px = u ? bigB : bigA;
    const float* pw = u ? bigA : bigB;
    size_t n = (size_t)NSEQ * CDIM;
    for (size_t i = (size_t)blockIdx.x * blockDim.x + threadIdx.x; i < n;
         i += (size_t)gridDim.x * blockDim.x) {
        g_x[i]  = px[i];
        g_wp[i] = pw[i];
    }
}

__global__ void lam_kernel(const float* __restrict__ s0, const float* __restrict__ s1,
                           const float* __restrict__ s2, const float* __restrict__ s3) {
    __shared__ float sa[64], sb[64];
    int t = threadIdx.x;
    sa[t] = s0[t] * s2[t];
    sb[t] = s1[t] * s3[t];
    __syncthreads();
    for (int s = 32; s > 0; s >>= 1) {
        if (t < s) { sa[t] += sa[t + s]; sb[t] += sb[t + s]; }
        __syncthreads();
    }
    if (t == 0) g_lam = expf(sa[0]) - expf(sb[0]) + 0.2f;
}

// ============ 128x128 tile, 8x8/thread fp32 GEMM building blocks ============
// smem layout: [k][m] (k-major), row stride 132 floats (16B aligned, low-conflict).

#define FRAG_LOAD(ar, br, AsT, BsT, k)                                   \
    do {                                                                 \
        *(float4*)&(ar)[0] = *(const float4*)&(AsT)[k][ty * 8];          \
        *(float4*)&(ar)[4] = *(const float4*)&(AsT)[k][ty * 8 + 4];      \
        *(float4*)&(br)[0] = *(const float4*)&(BsT)[k][tx * 8];          \
        *(float4*)&(br)[4] = *(const float4*)&(BsT)[k][tx * 8 + 4];      \
    } while (0)

#define FMA8x8(acc, ar, br)                                              \
    _Pragma("unroll")                                                    \
    for (int i_ = 0; i_ < 8; i_++)                                       \
        _Pragma("unroll")                                                \
        for (int j_ = 0; j_ < 8; j_++)                                   \
            (acc)[i_][j_] += (ar)[i_] * (br)[j_];

// ---------------- 1. qkv: NT  qkv[n,d] = sum_c x[n,c] * Wqkv[d,c] ----------------
__global__ void __launch_bounds__(256) qkv_t128(const float* __restrict__ Wqkv) {
    int d0 = blockIdx.x * 128;
    int n0 = blockIdx.y * 128;
    __shared__ float As[16][132];
    __shared__ float Bs[16][132];
    int tid = threadIdx.x;
    int ty = tid >> 4, tx = tid & 15;

    float acc[8][8] = {};
    for (int kt = 0; kt < CDIM; kt += 16) {
        #pragma unroll
        for (int l = 0; l < 8; l++) {
            int idx = tid + l * 256;           // 0..2047
            int r = idx >> 4, c = idx & 15;
            As[c][r] = g_x[(size_t)(n0 + r) * CDIM + kt + c];
            Bs[c][r] = Wqkv[(size_t)(d0 + r) * CDIM + kt + c];
        }
        __syncthreads();
        #pragma unroll
        for (int k = 0; k < 16; k++) {
            float ar[8], br[8];
            FRAG_LOAD(ar, br, As, Bs, k);
            FMA8x8(acc, ar, br);
        }
        __syncthreads();
    }
    #pragma unroll
    for (int i = 0; i < 8; i++) {
        float* orow = &g_qkv[(size_t)(n0 + ty * 8 + i) * (6 * CDIM) + d0 + tx * 8];
        *(float4*)&orow[0] = make_float4(acc[i][0], acc[i][1], acc[i][2], acc[i][3]);
        *(float4*)&orow[4] = make_float4(acc[i][4], acc[i][5], acc[i][6], acc[i][7]);
    }
}

// ---------------- 2. reorg + RoPE (verbatim, validated) ----------------
__global__ void __launch_bounds__(64) rope_naive() {
    int n = blockIdx.x;
    int h = blockIdx.y;
    int e = threadIdx.x;
    const float* row = g_qkv + (size_t)n * (6 * CDIM);
    int base = h * HD + e;
    float qa = row[0 * CDIM + base];
    float qb = row[1 * CDIM + base];
    float ka = row[2 * CDIM + base];
    float kb = row[3 * CDIM + base];
    float va = row[4 * CDIM + base];
    float vb = row[5 * CDIM + base];

    double invf = exp(-(double)e * (9.210340371976184 / 64.0));
    double th = (double)n * invf;
    float c = (float)cos(th);
    float s = (float)sin(th);

    size_t o = ((size_t)h * NSEQ + n) * D2;
    g_q[o + e]      = qa * c - qb * s;
    g_q[o + 64 + e] = qb * c + qa * s;
    g_k[o + e]      = ka * c - kb * s;
    g_k[o + 64 + e] = kb * c + ka * s;
    g_v[o + e]      = va;
    g_v[o + 64 + e] = vb;
}

// ---------------- 3. scores: per head S1=0.125*q1@k1^T, S2=0.125*q2@k2^T ----------------
// K runs 0..127; kt<64 accumulates into a1, kt>=64 into a2.
__global__ void __launch_bounds__(256) scores_t128() {
    int h  = blockIdx.z;
    int k0 = blockIdx.x * 128;
    int q0 = blockIdx.y * 128;
    __shared__ float Qs[16][132];
    __shared__ float Ks[16][132];
    int tid = threadIdx.x;
    int ty = tid >> 4, tx = tid & 15;

    const float* qb = g_q + ((size_t)h * NSEQ + q0) * D2;
    const float* kb = g_k + ((size_t)h * NSEQ + k0) * D2;

    float a1[8][8] = {}, a2[8][8] = {};
    #pragma unroll
    for (int kt = 0; kt < D2; kt += 16) {
        #pragma unroll
        for (int l = 0; l < 8; l++) {
            int idx = tid + l * 256;
            int r = idx >> 4, c = idx & 15;
            Qs[c][r] = qb[(size_t)r * D2 + kt + c];
            Ks[c][r] = kb[(size_t)r * D2 + kt + c];
        }
        __syncthreads();
        if (kt < 64) {
            #pragma unroll
            for (int k = 0; k < 16; k++) {
                float ar[8], br[8];
                FRAG_LOAD(ar, br, Qs, Ks, k);
                FMA8x8(a1, ar, br);
            }
        } else {
            #pragma unroll
            for (int k = 0; k < 16; k++) {
                float ar[8], br[8];
                FRAG_LOAD(ar, br, Qs, Ks, k);
                FMA8x8(a2, ar, br);
            }
        }
        __syncthreads();
    }

    #pragma unroll
    for (int i = 0; i < 8; i++) {
        size_t o = ((size_t)h * NSEQ + q0 + ty * 8 + i) * NSEQ + k0 + tx * 8;
        *(float4*)&g_S1[o]     = make_float4(a1[i][0]*0.125f, a1[i][1]*0.125f, a1[i][2]*0.125f, a1[i][3]*0.125f);
        *(float4*)&g_S1[o + 4] = make_float4(a1[i][4]*0.125f, a1[i][5]*0.125f, a1[i][6]*0.125f, a1[i][7]*0.125f);
        *(float4*)&g_S2[o]     = make_float4(a2[i][0]*0.125f, a2[i][1]*0.125f, a2[i][2]*0.125f, a2[i][3]*0.125f);
        *(float4*)&g_S2[o + 4] = make_float4(a2[i][4]*0.125f, a2[i][5]*0.125f, a2[i][6]*0.125f, a2[i][7]*0.125f);
    }
}

// ---------------- 4. softmax diff (verbatim, validated) ----------------
__global__ void __launch_bounds__(256) softmax_diff256() {
    size_t row = blockIdx.x;
    float* s1 = g_S1 + row * NSEQ;
    float* s2 = g_S2 + row * NSEQ;
    int tid = threadIdx.x;
    int lane = tid & 31, warp = tid >> 5;
    __shared__ float wr1[8], wr2[8];

    float v1[8], v2[8];
    float m1 = -1e30f, m2 = -1e30f;
    #pragma unroll
    for (int t = 0; t < 8; t++) {
        v1[t] = s1[tid + t * 256];
        v2[t] = s2[tid + t * 256];
        m1 = fmaxf(m1, v1[t]);
        m2 = fmaxf(m2, v2[t]);
    }
    #pragma unroll
    for (int o = 16; o > 0; o >>= 1) {
        m1 = fmaxf(m1, __shfl_xor_sync(0xffffffffu, m1, o));
        m2 = fmaxf(m2, __shfl_xor_sync(0xffffffffu, m2, o));
    }
    if (lane == 0) { wr1[warp] = m1; wr2[warp] = m2; }
    __syncthreads();
    m1 = wr1[0]; m2 = wr2[0];
    #pragma unroll
    for (int w = 1; w < 8; w++) { m1 = fmaxf(m1, wr1[w]); m2 = fmaxf(m2, wr2[w]); }
    __syncthreads();

    float l1 = 0.f, l2 = 0.f;
    #pragma unroll
    for (int t = 0; t < 8; t++) {
        v1[t] = __expf(v1[t] - m1);
        v2[t] = __expf(v2[t] - m2);
        l1 += v1[t];
        l2 += v2[t];
    }
    #pragma unroll
    for (int o = 16; o > 0; o >>= 1) {
        l1 += __shfl_xor_sync(0xffffffffu, l1, o);
        l2 += __shfl_xor_sync(0xffffffffu, l2, o);
    }
    if (lane == 0) { wr1[warp] = l1; wr2[warp] = l2; }
    __syncthreads();
    l1 = 0.f; l2 = 0.f;
    #pragma unroll
    for (int w = 0; w < 8; w++) { l1 += wr1[w]; l2 += wr2[w]; }

    float r1 = 1.0f / l1;
    float r2 = g_lam / l2;
    #pragma unroll
    for (int t = 0; t < 8; t++)
        s1[tid + t * 256] = v1[t] * r1 - v2[t] * r2;
}

// ---------------- 5. PV: per head out2d[n, h*128+d] = sum_j P[h,n,j]*V[h,j,d] ----------------
// NN GEMM [2048x2048]@[2048x128]; tile 128(n) x 128(d, full width), kstep 16.
__global__ void __launch_bounds__(256) pv_t128() {
    int h  = blockIdx.z;
    int n0 = blockIdx.y * 128;
    __shared__ float As[16][132];   // P transposed: [k][n]
    __shared__ float Bs[16][132];   // V natural:   [k][d]
    int tid = threadIdx.x;
    int ty = tid >> 4, tx = tid & 15;

    const float* P = g_S1 + (size_t)h * NSEQ * NSEQ;
    const float* V = g_v  + (size_t)h * NSEQ * D2;

    float acc[8][8] = {};
    for (int kt = 0; kt < NSEQ; kt += 16) {
        #pragma unroll
        for (int l = 0; l < 8; l++) {
            int idx = tid + l * 256;
            int ra = idx >> 4, ca = idx & 15;          // A: 128 rows x 16 k
            As[ca][ra] = P[(size_t)(n0 + ra) * NSEQ + kt + ca];
            int rb = idx >> 7, cb = idx & 127;         // B: 16 k x 128 d
            Bs[rb][cb] = V[(size_t)(kt + rb) * D2 + cb];
        }
        __syncthreads();
        #pragma unroll
        for (int k = 0; k < 16; k++) {
            float ar[8], br[8];
            FRAG_LOAD(ar, br, As, Bs, k);
            FMA8x8(acc, ar, br);
        }
        __syncthreads();
    }
    #pragma unroll
    for (int i = 0; i < 8; i++) {
        float* orow = &g_out2d[(size_t)(n0 + ty * 8 + i) * (2 * CDIM) + h * D2 + tx * 8];
        *(float4*)&orow[0] = make_float4(acc[i][0], acc[i][1], acc[i][2], acc[i][3]);
        *(float4*)&orow[4] = make_float4(acc[i][4], acc[i][5], acc[i][6], acc[i][7]);
    }
}

// ---------------- 6. proj: NT out[n,c] = sum_d out2d[n,d]*Wp[c,d] ----------------
__global__ void __launch_bounds__(256) proj_t128(float* __restrict__ out) {
    int c0 = blockIdx.x * 128;
    int n0 = blockIdx.y * 128;
    __shared__ float As[16][132];
    __shared__ float Bs[16][132];
    int tid = threadIdx.x;
    int ty = tid >> 4, tx = tid & 15;

    float acc[8][8] = {};
    for (int kt = 0; kt < 2 * CDIM; kt += 16) {
        #pragma unroll
        for (int l = 0; l < 8; l++) {
            int idx = tid + l * 256;
            int r = idx >> 4, c = idx & 15;
            As[c][r] = g_out2d[(size_t)(n0 + r) * (2 * CDIM) + kt + c];
            Bs[c][r] = g_wp[(size_t)(c0 + r) * (2 * CDIM) + kt + c];
        }
        __syncthreads();
        #pragma unroll
        for (int k = 0; k < 16; k++) {
            float ar[8], br[8];
            FRAG_LOAD(ar, br, As, Bs, k);
            FMA8x8(acc, ar, br);
        }
        __syncthreads();
    }
    #pragma unroll
    for (int i = 0; i < 8; i++) {
        float* orow = &out[(size_t)(n0 + ty * 8 + i) * CDIM + c0 + tx * 8];
        *(float4*)&orow[0] = make_float4(acc[i][0], acc[i][1], acc[i][2], acc[i][3]);
        *(float4*)&orow[4] = make_float4(acc[i][4], acc[i][5], acc[i][6], acc[i][7]);
    }
}

// ---------------- launch ----------------
extern "C" void kernel_launch(void* const* d_in, const int* in_sizes, int n_in,
                              void* d_out, int out_size) {
    const float* Wqkv = 0;
    const float* bigs[2] = {0, 0};
    const float* smalls[4] = {0, 0, 0, 0};
    int nbig = 0, nsmall = 0;
    for (int i = 0; i < n_in; i++) {
        const float* p = (const float*)d_in[i];
        if (in_sizes[i] == 6 * CDIM * CDIM) Wqkv = p;
        else if (in_sizes[i] == 2 * CDIM * CDIM) { if (nbig < 2) bigs[nbig++] = p; }
        else if (in_sizes[i] == HD) { if (nsmall < 4) smalls[nsmall++] = p; }
    }
    if (!Wqkv || nbig < 2 || nsmall < 4) {
        bigs[0]   = (const float*)d_in[0];
        Wqkv      = (const float*)d_in[1];
        bigs[1]   = (const float*)d_in[2];
        smalls[0] = (const float*)d_in[3];
        smalls[1] = (const float*)d_in[4];
        smalls[2] = (const float*)d_in[5];
        smalls[3] = (const float*)d_in[6];
    }
    float* out = (float*)d_out;

    detect_kernel<<<1, 256>>>(bigs[0], bigs[1]);
    route_kernel<<<512, 256>>>(bigs[0], bigs[1]);
    lam_kernel<<<1, 64>>>(smalls[0], smalls[1], smalls[2], smalls[3]);

    qkv_t128<<<dim3(48, 16), 256>>>(Wqkv);                // [2048,6144]
    rope_naive<<<dim3(NSEQ, NHEADS), 64>>>();
    scores_t128<<<dim3(16, 16, NHEADS), 256>>>();
    softmax_diff256<<<NHEADS * NSEQ, 256>>>();
    pv_t128<<<dim3(1, 16, NHEADS), 256>>>();              // [2048,128] per head
    proj_t128<<<dim3(8, 16), 256>>>(out);                 // [2048,1024]
}

// round 9
// speedup vs baseline: 88.1864x; 2.7221x over previous
#include <cuda_runtime.h>
#include <math.h>

#define NHEADS 16
#define NSEQ   2048
#define CDIM   1024
#define HD     64
#define D2     128

// ---------------- scratch ----------------
__device__ float g_x[(size_t)NSEQ * CDIM];
__device__ float g_wp[(size_t)CDIM * 2 * CDIM];
__device__ float g_qkv[(size_t)NSEQ * 6 * CDIM];
__device__ float g_q[(size_t)NHEADS * NSEQ * D2];
__device__ float g_k[(size_t)NHEADS * NSEQ * D2];
__device__ float g_v[(size_t)NHEADS * NSEQ * D2];
__device__ float g_S1[(size_t)NHEADS * NSEQ * NSEQ];
__device__ float g_S2[(size_t)NHEADS * NSEQ * NSEQ];
__device__ float g_out2d[(size_t)NSEQ * 2 * CDIM];
__device__ float g_lam;
__device__ int   g_use;

// ---------------- tf32 helpers ----------------
__device__ __forceinline__ unsigned f2tf(float f) {
    unsigned r;
    asm("cvt.rna.tf32.f32 %0, %1;" : "=r"(r) : "f"(f));
    return r;
}

#define MMA_TF32(d, a, b)                                                      \
    asm volatile(                                                              \
        "mma.sync.aligned.m16n8k8.row.col.f32.tf32.tf32.f32 "                  \
        "{%0,%1,%2,%3}, {%4,%5,%6,%7}, {%8,%9}, {%0,%1,%2,%3};"                \
        : "+f"((d)[0]), "+f"((d)[1]), "+f"((d)[2]), "+f"((d)[3])               \
        : "r"((a)[0]), "r"((a)[1]), "r"((a)[2]), "r"((a)[3]),                  \
          "r"((b)[0]), "r"((b)[1]))

// Fragment gather from [m][k]-layout smem (stride 36) + 16 MMAs for one k=8 chunk.
#define NT_KCHUNK(acc, As, Bs, kc)                                             \
    do {                                                                       \
        unsigned a_[2][4], b_[8][2];                                           \
        _Pragma("unroll")                                                      \
        for (int mt = 0; mt < 2; mt++) {                                       \
            int m_ = wm * 32 + mt * 16;                                        \
            a_[mt][0] = (As)[m_ + g][(kc)*8 + tig];                            \
            a_[mt][1] = (As)[m_ + g + 8][(kc)*8 + tig];                        \
            a_[mt][2] = (As)[m_ + g][(kc)*8 + tig + 4];                        \
            a_[mt][3] = (As)[m_ + g + 8][(kc)*8 + tig + 4];                    \
        }                                                                      \
        _Pragma("unroll")                                                      \
        for (int nt = 0; nt < 8; nt++) {                                       \
            int n_ = wn * 64 + nt * 8 + g;                                     \
            b_[nt][0] = (Bs)[n_][(kc)*8 + tig];                                \
            b_[nt][1] = (Bs)[n_][(kc)*8 + tig + 4];                            \
        }                                                                      \
        _Pragma("unroll")                                                      \
        for (int mt = 0; mt < 2; mt++)                                         \
            _Pragma("unroll")                                                  \
            for (int nt = 0; nt < 8; nt++)                                     \
                MMA_TF32((acc)[mt][nt], a_[mt], b_[nt]);                       \
    } while (0)

// ---------------- input disambiguation (verbatim, validated) ----------------
__global__ void detect_kernel(const float* __restrict__ bigA, const float* __restrict__ bigB) {
    __shared__ float sa[256], sb[256];
    int t = threadIdx.x;
    float a = 0.f, b = 0.f;
    for (int i = t; i < 4096; i += 256) { a += fabsf(bigA[i]); b += fabsf(bigB[i]); }
    sa[t] = a; sb[t] = b;
    __syncthreads();
    for (int s = 128; s > 0; s >>= 1) {
        if (t < s) { sa[t] += sa[t + s]; sb[t] += sb[t + s]; }
        __syncthreads();
    }
    if (t == 0) g_use = (sb[0] > sa[0]) ? 1 : 0;
}

__global__ void route_kernel(const float* __restrict__ bigA, const float* __restrict__ bigB) {
    int u = g_use;
    const float* px = u ? bigB : bigA;
    const float* pw = u ? bigA : bigB;
    size_t n = (size_t)NSEQ * CDIM;
    for (size_t i = (size_t)blockIdx.x * blockDim.x + threadIdx.x; i < n;
         i += (size_t)gridDim.x * blockDim.x) {
        g_x[i]  = px[i];
        g_wp[i] = pw[i];
    }
}

__global__ void lam_kernel(const float* __restrict__ s0, const float* __restrict__ s1,
                           const float* __restrict__ s2, const float* __restrict__ s3) {
    __shared__ float sa[64], sb[64];
    int t = threadIdx.x;
    sa[t] = s0[t] * s2[t];
    sb[t] = s1[t] * s3[t];
    __syncthreads();
    for (int s = 32; s > 0; s >>= 1) {
        if (t < s) { sa[t] += sa[t + s]; sb[t] += sb[t + s]; }
        __syncthreads();
    }
    if (t == 0) g_lam = expf(sa[0]) - expf(sb[0]) + 0.2f;
}

// ---------------- 1. qkv: NT tf32  qkv[n,d] = sum_c x[n,c] * Wqkv[d,c] ----------------
__global__ void __launch_bounds__(256, 2) qkv_mma(const float* __restrict__ Wqkv) {
    __shared__ unsigned As[128][36];
    __shared__ unsigned Bs[128][36];
    int tid = threadIdx.x, lane = tid & 31, warp = tid >> 5;
    int g = lane >> 2, tig = lane & 3;
    int wm = warp >> 1, wn = warp & 1;
    int n0 = blockIdx.y * 128, d0 = blockIdx.x * 128;

    float acc[2][8][4] = {};
    for (int kt = 0; kt < CDIM; kt += 32) {
        #pragma unroll
        for (int p = 0; p < 4; p++) {
            int r = (tid >> 3) + p * 32, c = (tid & 7) * 4;
            float4 va = *(const float4*)&g_x[(size_t)(n0 + r) * CDIM + kt + c];
            float4 vb = *(const float4*)&Wqkv[(size_t)(d0 + r) * CDIM + kt + c];
            As[r][c] = f2tf(va.x); As[r][c+1] = f2tf(va.y); As[r][c+2] = f2tf(va.z); As[r][c+3] = f2tf(va.w);
            Bs[r][c] = f2tf(vb.x); Bs[r][c+1] = f2tf(vb.y); Bs[r][c+2] = f2tf(vb.z); Bs[r][c+3] = f2tf(vb.w);
        }
        __syncthreads();
        #pragma unroll
        for (int kc = 0; kc < 4; kc++) NT_KCHUNK(acc, As, Bs, kc);
        __syncthreads();
    }
    #pragma unroll
    for (int mt = 0; mt < 2; mt++)
        #pragma unroll
        for (int nt = 0; nt < 8; nt++) {
            int row = n0 + wm * 32 + mt * 16 + g;
            int col = d0 + wn * 64 + nt * 8 + 2 * tig;
            *(float2*)&g_qkv[(size_t)row * (6*CDIM) + col] = make_float2(acc[mt][nt][0], acc[mt][nt][1]);
            *(float2*)&g_qkv[(size_t)(row + 8) * (6*CDIM) + col] = make_float2(acc[mt][nt][2], acc[mt][nt][3]);
        }
}

// ---------------- 2. reorg + RoPE (verbatim, validated) ----------------
__global__ void __launch_bounds__(64) rope_naive() {
    int n = blockIdx.x;
    int h = blockIdx.y;
    int e = threadIdx.x;
    const float* row = g_qkv + (size_t)n * (6 * CDIM);
    int base = h * HD + e;
    float qa = row[0 * CDIM + base];
    float qb = row[1 * CDIM + base];
    float ka = row[2 * CDIM + base];
    float kb = row[3 * CDIM + base];
    float va = row[4 * CDIM + base];
    float vb = row[5 * CDIM + base];

    double invf = exp(-(double)e * (9.210340371976184 / 64.0));
    double th = (double)n * invf;
    float c = (float)cos(th);
    float s = (float)sin(th);

    size_t o = ((size_t)h * NSEQ + n) * D2;
    g_q[o + e]      = qa * c - qb * s;
    g_q[o + 64 + e] = qb * c + qa * s;
    g_k[o + e]      = ka * c - kb * s;
    g_k[o + 64 + e] = kb * c + ka * s;
    g_v[o + e]      = va;
    g_v[o + 64 + e] = vb;
}

// ---------------- 3. scores: batched NT tf32, z = head*2 + half ----------------
__global__ void __launch_bounds__(256, 2) scores_mma() {
    __shared__ unsigned As[128][36];
    __shared__ unsigned Bs[128][36];
    int tid = threadIdx.x, lane = tid & 31, warp = tid >> 5;
    int g = lane >> 2, tig = lane & 3;
    int wm = warp >> 1, wn = warp & 1;
    int z = blockIdx.z, h = z >> 1, half = z & 1;
    int q0 = blockIdx.y * 128, k0 = blockIdx.x * 128;

    const float* A = g_q + (size_t)h * NSEQ * D2 + half * 64;
    const float* B = g_k + (size_t)h * NSEQ * D2 + half * 64;
    float* C = (half ? g_S2 : g_S1) + (size_t)h * NSEQ * NSEQ;

    float acc[2][8][4] = {};
    #pragma unroll
    for (int kt = 0; kt < 64; kt += 32) {
        #pragma unroll
        for (int p = 0; p < 4; p++) {
            int r = (tid >> 3) + p * 32, c = (tid & 7) * 4;
            float4 va = *(const float4*)&A[(size_t)(q0 + r) * D2 + kt + c];
            float4 vb = *(const float4*)&B[(size_t)(k0 + r) * D2 + kt + c];
            As[r][c] = f2tf(va.x); As[r][c+1] = f2tf(va.y); As[r][c+2] = f2tf(va.z); As[r][c+3] = f2tf(va.w);
            Bs[r][c] = f2tf(vb.x); Bs[r][c+1] = f2tf(vb.y); Bs[r][c+2] = f2tf(vb.z); Bs[r][c+3] = f2tf(vb.w);
        }
        __syncthreads();
        #pragma unroll
        for (int kc = 0; kc < 4; kc++) NT_KCHUNK(acc, As, Bs, kc);
        __syncthreads();
    }
    #pragma unroll
    for (int mt = 0; mt < 2; mt++)
        #pragma unroll
        for (int nt = 0; nt < 8; nt++) {
            int row = q0 + wm * 32 + mt * 16 + g;
            int col = k0 + wn * 64 + nt * 8 + 2 * tig;
            *(float2*)&C[(size_t)row * NSEQ + col] =
                make_float2(acc[mt][nt][0] * 0.125f, acc[mt][nt][1] * 0.125f);
            *(float2*)&C[(size_t)(row + 8) * NSEQ + col] =
                make_float2(acc[mt][nt][2] * 0.125f, acc[mt][nt][3] * 0.125f);
        }
}

// ---------------- 4. softmax diff (verbatim, validated) ----------------
__global__ void __launch_bounds__(256) softmax_diff256() {
    size_t row = blockIdx.x;
    float* s1 = g_S1 + row * NSEQ;
    float* s2 = g_S2 + row * NSEQ;
    int tid = threadIdx.x;
    int lane = tid & 31, warp = tid >> 5;
    __shared__ float wr1[8], wr2[8];

    float v1[8], v2[8];
    float m1 = -1e30f, m2 = -1e30f;
    #pragma unroll
    for (int t = 0; t < 8; t++) {
        v1[t] = s1[tid + t * 256];
        v2[t] = s2[tid + t * 256];
        m1 = fmaxf(m1, v1[t]);
        m2 = fmaxf(m2, v2[t]);
    }
    #pragma unroll
    for (int o = 16; o > 0; o >>= 1) {
        m1 = fmaxf(m1, __shfl_xor_sync(0xffffffffu, m1, o));
        m2 = fmaxf(m2, __shfl_xor_sync(0xffffffffu, m2, o));
    }
    if (lane == 0) { wr1[warp] = m1; wr2[warp] = m2; }
    __syncthreads();
    m1 = wr1[0]; m2 = wr2[0];
    #pragma unroll
    for (int w = 1; w < 8; w++) { m1 = fmaxf(m1, wr1[w]); m2 = fmaxf(m2, wr2[w]); }
    __syncthreads();

    float l1 = 0.f, l2 = 0.f;
    #pragma unroll
    for (int t = 0; t < 8; t++) {
        v1[t] = __expf(v1[t] - m1);
        v2[t] = __expf(v2[t] - m2);
        l1 += v1[t];
        l2 += v2[t];
    }
    #pragma unroll
    for (int o = 16; o > 0; o >>= 1) {
        l1 += __shfl_xor_sync(0xffffffffu, l1, o);
        l2 += __shfl_xor_sync(0xffffffffu, l2, o);
    }
    if (lane == 0) { wr1[warp] = l1; wr2[warp] = l2; }
    __syncthreads();
    l1 = 0.f; l2 = 0.f;
    #pragma unroll
    for (int w = 0; w < 8; w++) { l1 += wr1[w]; l2 += wr2[w]; }

    float r1 = 1.0f / l1;
    float r2 = g_lam / l2;
    #pragma unroll
    for (int t = 0; t < 8; t++)
        s1[tid + t * 256] = v1[t] * r1 - v2[t] * r2;
}

// ---------------- 5. PV: NN tf32 per head: out2d[n, h*128+d] = sum_j P[h,n,j]*V[h,j,d] ----------------
__global__ void __launch_bounds__(256, 2) pv_mma() {
    __shared__ unsigned As[128][36];    // P: [n][k], stride 36
    __shared__ unsigned Bs[32][132];    // V: [k][d], stride 132
    int tid = threadIdx.x, lane = tid & 31, warp = tid >> 5;
    int g = lane >> 2, tig = lane & 3;
    int wm = warp >> 1, wn = warp & 1;
    int n0 = blockIdx.x * 128, h = blockIdx.y;

    const float* P = g_S1 + (size_t)h * NSEQ * NSEQ;
    const float* V = g_v  + (size_t)h * NSEQ * D2;

    float acc[2][8][4] = {};
    for (int kt = 0; kt < NSEQ; kt += 32) {
        #pragma unroll
        for (int p = 0; p < 4; p++) {
            int r = (tid >> 3) + p * 32, c = (tid & 7) * 4;
            float4 va = *(const float4*)&P[(size_t)(n0 + r) * NSEQ + kt + c];
            As[r][c] = f2tf(va.x); As[r][c+1] = f2tf(va.y); As[r][c+2] = f2tf(va.z); As[r][c+3] = f2tf(va.w);
            int k = (tid >> 5) + p * 8, c4 = (tid & 31) * 4;
            float4 vb = *(const float4*)&V[(size_t)(kt + k) * D2 + c4];
            Bs[k][c4] = f2tf(vb.x); Bs[k][c4+1] = f2tf(vb.y); Bs[k][c4+2] = f2tf(vb.z); Bs[k][c4+3] = f2tf(vb.w);
        }
        __syncthreads();
        #pragma unroll
        for (int kc = 0; kc < 4; kc++) {
            unsigned a_[2][4], b_[8][2];
            #pragma unroll
            for (int mt = 0; mt < 2; mt++) {
                int m_ = wm * 32 + mt * 16;
                a_[mt][0] = As[m_ + g][kc*8 + tig];
                a_[mt][1] = As[m_ + g + 8][kc*8 + tig];
                a_[mt][2] = As[m_ + g][kc*8 + tig + 4];
                a_[mt][3] = As[m_ + g + 8][kc*8 + tig + 4];
            }
            #pragma unroll
            for (int nt = 0; nt < 8; nt++) {
                int n_ = wn * 64 + nt * 8 + g;
                b_[nt][0] = Bs[kc*8 + tig][n_];
                b_[nt][1] = Bs[kc*8 + tig + 4][n_];
            }
            #pragma unroll
            for (int mt = 0; mt < 2; mt++)
                #pragma unroll
                for (int nt = 0; nt < 8; nt++)
                    MMA_TF32(acc[mt][nt], a_[mt], b_[nt]);
        }
        __syncthreads();
    }
    #pragma unroll
    for (int mt = 0; mt < 2; mt++)
        #pragma unroll
        for (int nt = 0; nt < 8; nt++) {
            int row = n0 + wm * 32 + mt * 16 + g;
            int col = wn * 64 + nt * 8 + 2 * tig;
            *(float2*)&g_out2d[(size_t)row * (2*CDIM) + h * D2 + col] =
                make_float2(acc[mt][nt][0], acc[mt][nt][1]);
            *(float2*)&g_out2d[(size_t)(row + 8) * (2*CDIM) + h * D2 + col] =
                make_float2(acc[mt][nt][2], acc[mt][nt][3]);
        }
}

// ---------------- 6. proj: NT tf32  out[n,c] = sum_d out2d[n,d]*Wp[c,d] ----------------
__global__ void __launch_bounds__(256, 2) proj_mma(float* __restrict__ out) {
    __shared__ unsigned As[128][36];
    __shared__ unsigned Bs[128][36];
    int tid = threadIdx.x, lane = tid & 31, warp = tid >> 5;
    int g = lane >> 2, tig = lane & 3;
    int wm = warp >> 1, wn = warp & 1;
    int n0 = blockIdx.y * 128, c0 = blockIdx.x * 128;

    float acc[2][8][4] = {};
    for (int kt = 0; kt < 2 * CDIM; kt += 32) {
        #pragma unroll
        for (int p = 0; p < 4; p++) {
            int r = (tid >> 3) + p * 32, c = (tid & 7) * 4;
            float4 va = *(const float4*)&g_out2d[(size_t)(n0 + r) * (2*CDIM) + kt + c];
            float4 vb = *(const float4*)&g_wp[(size_t)(c0 + r) * (2*CDIM) + kt + c];
            As[r][c] = f2tf(va.x); As[r][c+1] = f2tf(va.y); As[r][c+2] = f2tf(va.z); As[r][c+3] = f2tf(va.w);
            Bs[r][c] = f2tf(vb.x); Bs[r][c+1] = f2tf(vb.y); Bs[r][c+2] = f2tf(vb.z); Bs[r][c+3] = f2tf(vb.w);
        }
        __syncthreads();
        #pragma unroll
        for (int kc = 0; kc < 4; kc++) NT_KCHUNK(acc, As, Bs, kc);
        __syncthreads();
    }
    #pragma unroll
    for (int mt = 0; mt < 2; mt++)
        #pragma unroll
        for (int nt = 0; nt < 8; nt++) {
            int row = n0 + wm * 32 + mt * 16 + g;
            int col = c0 + wn * 64 + nt * 8 + 2 * tig;
            *(float2*)&out[(size_t)row * CDIM + col] = make_float2(acc[mt][nt][0], acc[mt][nt][1]);
            *(float2*)&out[(size_t)(row + 8) * CDIM + col] = make_float2(acc[mt][nt][2], acc[mt][nt][3]);
        }
}

// ---------------- launch ----------------
extern "C" void kernel_launch(void* const* d_in, const int* in_sizes, int n_in,
                              void* d_out, int out_size) {
    const float* Wqkv = 0;
    const float* bigs[2] = {0, 0};
    const float* smalls[4] = {0, 0, 0, 0};
    int nbig = 0, nsmall = 0;
    for (int i = 0; i < n_in; i++) {
        const float* p = (const float*)d_in[i];
        if (in_sizes[i] == 6 * CDIM * CDIM) Wqkv = p;
        else if (in_sizes[i] == 2 * CDIM * CDIM) { if (nbig < 2) bigs[nbig++] = p; }
        else if (in_sizes[i] == HD) { if (nsmall < 4) smalls[nsmall++] = p; }
    }
    if (!Wqkv || nbig < 2 || nsmall < 4) {
        bigs[0]   = (const float*)d_in[0];
        Wqkv      = (const float*)d_in[1];
        bigs[1]   = (const float*)d_in[2];
        smalls[0] = (const float*)d_in[3];
        smalls[1] = (const float*)d_in[4];
        smalls[2] = (const float*)d_in[5];
        smalls[3] = (const float*)d_in[6];
    }
    float* out = (float*)d_out;

    detect_kernel<<<1, 256>>>(bigs[0], bigs[1]);
    route_kernel<<<512, 256>>>(bigs[0], bigs[1]);
    lam_kernel<<<1, 64>>>(smalls[0], smalls[1], smalls[2], smalls[3]);

    qkv_mma<<<dim3(48, 16), 256>>>(Wqkv);                 // [2048,6144]
    rope_naive<<<dim3(NSEQ, NHEADS), 64>>>();
    scores_mma<<<dim3(16, 16, 2 * NHEADS), 256>>>();      // batched head*half
    softmax_diff256<<<NHEADS * NSEQ, 256>>>();
    pv_mma<<<dim3(16, NHEADS), 256>>>();                  // [2048,128] per head
    proj_mma<<<dim3(8, 16), 256>>>(out);                  // [2048,1024]
}